// round 1
// baseline (speedup 1.0000x reference)
#include <cuda_runtime.h>
#include <cuda_bf16.h>
#include <cstdint>

// Embedding gather: out[b, t, :] = weight[idxes[b, t], :]
// idxes: [8, 2048] int32  (in_sizes[0] = 16384)
// weight: [50257, 1024] float32
// out:   [8, 2048, 1024] float32
//
// One CTA per output row. 256 threads x float4 = 4096 B/row, fully coalesced.

#define FEATURES 1024
#define VEC4_PER_ROW (FEATURES / 4)   // 256

__global__ __launch_bounds__(256) void embedding_gather_kernel(
    const int* __restrict__ idxes,
    const float4* __restrict__ weight,
    float4* __restrict__ out,
    int n_rows)
{
    int row = blockIdx.x;
    if (row >= n_rows) return;

    int src = idxes[row];  // broadcast load, L1/L2-hit for all but first thread

    const float4* __restrict__ wsrc = weight + (size_t)src * VEC4_PER_ROW;
    float4* __restrict__ dst = out + (size_t)row * VEC4_PER_ROW;

    int t = threadIdx.x;           // 0..255, exactly VEC4_PER_ROW
    dst[t] = __ldg(&wsrc[t]);
}

extern "C" void kernel_launch(void* const* d_in, const int* in_sizes, int n_in,
                              void* d_out, int out_size)
{
    const int*    idxes  = (const int*)d_in[0];
    const float4* weight = (const float4*)d_in[1];
    float4*       out    = (float4*)d_out;

    int n_rows = in_sizes[0];      // 8 * 2048 = 16384

    embedding_gather_kernel<<<n_rows, 256>>>(idxes, weight, out, n_rows);
}

// round 2
// speedup vs baseline: 1.3289x; 1.3289x over previous
#include <cuda_runtime.h>
#include <cuda_bf16.h>
#include <cstdint>

// Embedding gather: out[b, t, :] = weight[idxes[b, t], :]
// idxes: [8, 2048] int32  (in_sizes[0] = 16384)
// weight: [50257, 1024] float32
// out:   [8, 2048, 1024] float32
//
// MLP-batched version: each CTA handles ROWS_PER_CTA rows; each thread
// front-batches ROWS_PER_CTA independent LDG.128s (one float4 per row,
// same column slot) before any store, so the warp has 8 loads in flight
// instead of 1. This converts a latency-bound profile (DRAM 43%) into a
// bandwidth-bound one.

#define FEATURES 1024
#define VEC4_PER_ROW (FEATURES / 4)   // 256
#define ROWS_PER_CTA 8

__global__ __launch_bounds__(256) void embedding_gather_mlp_kernel(
    const int* __restrict__ idxes,
    const float4* __restrict__ weight,
    float4* __restrict__ out,
    int n_rows)
{
    const int t = threadIdx.x;                     // 0..255 = column slot
    const int base = blockIdx.x * ROWS_PER_CTA;

    if (base + ROWS_PER_CTA <= n_rows) {
        // Fast path: full tile of 8 rows.
        int idx[ROWS_PER_CTA];
#pragma unroll
        for (int r = 0; r < ROWS_PER_CTA; r++)
            idx[r] = idxes[base + r];              // broadcast loads

        float4 v[ROWS_PER_CTA];
#pragma unroll
        for (int r = 0; r < ROWS_PER_CTA; r++)
            v[r] = __ldg(weight + (size_t)idx[r] * VEC4_PER_ROW + t);

#pragma unroll
        for (int r = 0; r < ROWS_PER_CTA; r++)
            out[(size_t)(base + r) * VEC4_PER_ROW + t] = v[r];
    } else {
        // Tail path (n_rows not a multiple of ROWS_PER_CTA).
        for (int r = 0; r < ROWS_PER_CTA; r++) {
            int row = base + r;
            if (row >= n_rows) break;
            int src = idxes[row];
            out[(size_t)row * VEC4_PER_ROW + t] =
                __ldg(weight + (size_t)src * VEC4_PER_ROW + t);
        }
    }
}

extern "C" void kernel_launch(void* const* d_in, const int* in_sizes, int n_in,
                              void* d_out, int out_size)
{
    const int*    idxes  = (const int*)d_in[0];
    const float4* weight = (const float4*)d_in[1];
    float4*       out    = (float4*)d_out;

    int n_rows = in_sizes[0];      // 8 * 2048 = 16384
    int n_ctas = (n_rows + ROWS_PER_CTA - 1) / ROWS_PER_CTA;

    embedding_gather_mlp_kernel<<<n_ctas, 256>>>(idxes, weight, out, n_rows);
}